// round 3
// baseline (speedup 1.0000x reference)
#include <cuda_runtime.h>
#include <cuda_bf16.h>
#include <cuda_fp16.h>
#include <math.h>

#define N_NODES 100000
#define N_EDGES 800000
#define D_DATA  100
#define H_DIM   256
#define N_CLS   47
#define K_STEPS 10
#define D_VEC   25          // D_DATA/4: float4s per row (fp32) / uint2s per row (fp16)

// ---------------- static device scratch ----------------
__device__ __half g_h0[(size_t)N_NODES * D_DATA];    // 20 MB
__device__ __half g_h1[(size_t)N_NODES * D_DATA];    // 20 MB
__device__ int    d_cnt[N_NODES];
__device__ int    d_ptr[N_NODES + 1];
__device__ int    d_cursor[N_NODES];
__device__ float  d_norm[N_NODES];
__device__ float  d_n2[N_NODES];
__device__ int    d_csr[N_EDGES];

// ---------------- f32x2 packed helpers ----------------
#define FMA2(acc, a, b) \
    asm("fma.rn.f32x2 %0, %1, %2, %0;" : "+l"(acc) : "l"(a), "l"(b))
#define PACK_DUP(dst, v) \
    asm("mov.b64 %0, {%1, %1};" : "=l"(dst) : "r"(__float_as_uint(v)))
#define UNPACK2(lo, hi, v) \
    asm("mov.b64 {%0, %1}, %2;" : "=f"(lo), "=f"(hi) : "l"(v))

// ---------------- CSR build ----------------
__global__ void zero_cnt_kernel() {
    int i = blockIdx.x * blockDim.x + threadIdx.x;
    if (i < N_NODES) d_cnt[i] = 0;
}

__global__ void count_kernel(const int* __restrict__ dst) {
    int e = blockIdx.x * blockDim.x + threadIdx.x;
    if (e < N_EDGES) atomicAdd(&d_cnt[dst[e]], 1);
}

#define SCAN_T 1024
#define SCAN_CH 98   // ceil(100000/1024)
__global__ void scan_kernel() {
    __shared__ int part[SCAN_T];
    int t = threadIdx.x;
    int beg = t * SCAN_CH;
    int end = beg + SCAN_CH; if (end > N_NODES) end = N_NODES;
    if (beg > N_NODES) beg = N_NODES;
    int s = 0;
    for (int i = beg; i < end; i++) s += d_cnt[i];
    part[t] = s;
    __syncthreads();
    for (int off = 1; off < SCAN_T; off <<= 1) {
        int v = (t >= off) ? part[t - off] : 0;
        __syncthreads();
        part[t] += v;
        __syncthreads();
    }
    int run = part[t] - s;
    for (int i = beg; i < end; i++) {
        d_ptr[i] = run;
        d_cursor[i] = run;
        run += d_cnt[i];
    }
    if (t == SCAN_T - 1) d_ptr[N_NODES] = part[SCAN_T - 1];
}

__global__ void norm_kernel() {
    int i = blockIdx.x * blockDim.x + threadIdx.x;
    if (i < N_NODES) {
        float dg = (float)d_cnt[i];
        float nm = rsqrtf(fmaxf(dg, 1.0f));
        d_norm[i] = nm;
        d_n2[i] = nm * nm;
    }
}

__global__ void fill_kernel(const int* __restrict__ src, const int* __restrict__ dst) {
    int e = blockIdx.x * blockDim.x + threadIdx.x;
    if (e < N_EDGES) {
        int d = dst[e];
        int p = atomicAdd(&d_cursor[d], 1);
        d_csr[p] = src[e];
    }
}

// ---------------- propagation ----------------
static __device__ __forceinline__ uint2 pack4_h(float a, float b, float c, float d) {
    __half2 p0 = __floats2half2_rn(a, b);
    __half2 p1 = __floats2half2_rn(c, d);
    uint2 r;
    r.x = *(unsigned int*)&p0;
    r.y = *(unsigned int*)&p1;
    return r;
}

// g0 = norm * x   (fp16 store)
__global__ void init_g_kernel(const float4* __restrict__ x) {
    int idx = blockIdx.x * blockDim.x + threadIdx.x;
    if (idx < N_NODES * D_VEC) {
        int node = idx / D_VEC;
        float nm = d_norm[node];
        float4 v = x[idx];
        ((uint2*)g_h0)[idx] = pack4_h(v.x * nm, v.y * nm, v.z * nm, v.w * nm);
    }
}

// Warp per node, fp16 gather (1 LDG.64 per edge per active lane, 25 lanes),
// fp32 accumulate, fp16 store.
// non-last: g' = 0.9*n2*agg + 0.1*norm*x ; last: h = 0.9*norm*agg + 0.1*x
__global__ void prop_kernel(const uint2* __restrict__ gin,
                            uint2* __restrict__ gout,
                            const float4* __restrict__ x,
                            int last) {
    int warp = (blockIdx.x * blockDim.x + threadIdx.x) >> 5;
    int lane = threadIdx.x & 31;
    if (warp >= N_NODES) return;
    int beg = d_ptr[warp];
    int end = d_ptr[warp + 1];

    float a0 = 0.f, a1 = 0.f, a2 = 0.f, a3 = 0.f;
    bool act = lane < D_VEC;

    for (int base = beg; base < end; base += 32) {
        int n = end - base; if (n > 32) n = 32;
        int idx = (lane < n) ? d_csr[base + lane] : 0;
        #pragma unroll 4
        for (int e = 0; e < n; e++) {
            int s = __shfl_sync(0xffffffffu, idx, e);
            if (act) {
                uint2 r = gin[s * D_VEC + lane];
                float2 f0 = __half22float2(*(__half2*)&r.x);
                float2 f1 = __half22float2(*(__half2*)&r.y);
                a0 += f0.x; a1 += f0.y; a2 += f1.x; a3 += f1.y;
            }
        }
    }

    float ni = d_norm[warp];
    float s1, s2;
    if (last) { s1 = 0.9f * ni;         s2 = 0.1f; }
    else      { s1 = 0.9f * d_n2[warp]; s2 = 0.1f * ni; }

    if (act) {
        float4 xv = x[warp * D_VEC + lane];
        gout[warp * D_VEC + lane] = pack4_h(
            s1 * a0 + s2 * xv.x,
            s1 * a1 + s2 * xv.y,
            s1 * a2 + s2 * xv.z,
            s1 * a3 + s2 * xv.w);
    }
}

// ---------------- fused MLP: logits = relu(h@W1+b1)@W2+b2 ----------------
#define TM 32
#define HS_STRIDE 104
#define W2T_STRIDE 258
#define MLP_THREADS 256

#define SM_W1P  (D_DATA * H_DIM)            // 25600
#define SM_W2T  (48 * W2T_STRIDE)           // 12384
#define SM_B1   (H_DIM)
#define SM_B2   (48)
#define SM_HS   (TM * HS_STRIDE)            // 3328
#define SM_ZS   (TM * H_DIM)                // 8192
#define MLP_SMEM_FLOATS (SM_W1P + SM_W2T + SM_B1 + SM_B2 + SM_HS + SM_ZS)

__global__ void __launch_bounds__(MLP_THREADS, 1)
mlp_kernel(const __half* __restrict__ h,
           const float* __restrict__ W1, const float* __restrict__ b1,
           const float* __restrict__ W2, const float* __restrict__ b2,
           float* __restrict__ out) {
    extern __shared__ float sm[];
    float* W1p = sm;                        // permuted, 16B-unit layout
    float* W2t = W1p + SM_W1P;              // [c][j], stride 258
    float* b1s = W2t + SM_W2T;
    float* b2s = b1s + SM_B1;
    float* hs  = b2s + SM_B2;               // [m][104]
    float* zs  = hs + SM_HS;                // [m][256]

    int tid = threadIdx.x;

    {
        const float4* W1v = (const float4*)W1;
        float4* W1pv = (float4*)W1p;
        for (int i = tid; i < D_DATA * 64; i += MLP_THREADS) {
            int d = i >> 6, u = i & 63;
            int k = u & 3, jg = u >> 2;
            W1pv[(d * 4 + k) * 16 + jg] = W1v[i];
        }
    }
    for (int i = tid; i < 48 * H_DIM; i += MLP_THREADS) {
        int c = i >> 8, j = i & 255;
        W2t[c * W2T_STRIDE + j] = (c < N_CLS) ? W2[j * N_CLS + c] : 0.f;
    }
    for (int i = tid; i < H_DIM; i += MLP_THREADS) b1s[i] = b1[i];
    if (tid < 48) b2s[tid] = (tid < N_CLS) ? b2[tid] : 0.f;
    __syncthreads();

    int jg = tid & 15, mg = tid >> 4;
    int j0 = jg * 16, m0 = mg * 2;
    int cg = tid & 15, mg2 = tid >> 4;
    int c0 = cg * 3, mm0 = mg2 * 2;

    const ulonglong2* W1q = (const ulonglong2*)W1p;

    int n_tiles = N_NODES / TM;   // 3125 exact
    for (int tile = blockIdx.x; tile < n_tiles; tile += gridDim.x) {
        int node0 = tile * TM;

        // load fp16 h tile -> fp32 smem (coalesced halves, convert in flight)
        {
            const __half2* hrow = (const __half2*)(h + (size_t)node0 * D_DATA);
            for (int i = tid; i < TM * (D_DATA / 2); i += MLP_THREADS) {
                int m = i / (D_DATA / 2), d2 = i - m * (D_DATA / 2);
                float2 f = __half22float2(hrow[m * (D_DATA / 2) + d2]);
                hs[m * HS_STRIDE + d2 * 2]     = f.x;
                hs[m * HS_STRIDE + d2 * 2 + 1] = f.y;
            }
        }
        __syncthreads();

        // ---- phase 1: z = relu(h@W1 + b1) ----
        unsigned long long acc[2][8];
        #pragma unroll
        for (int k = 0; k < 4; k++) {
            unsigned long long blo = *(const unsigned long long*)(b1s + j0 + k * 4);
            unsigned long long bhi = *(const unsigned long long*)(b1s + j0 + k * 4 + 2);
            acc[0][k * 2]     = blo; acc[0][k * 2 + 1] = bhi;
            acc[1][k * 2]     = blo; acc[1][k * 2 + 1] = bhi;
        }

        #pragma unroll 2
        for (int d = 0; d < D_DATA; d++) {
            unsigned long long w[8];
            #pragma unroll
            for (int k = 0; k < 4; k++) {
                ulonglong2 wq = W1q[(d * 4 + k) * 16 + jg];
                w[k * 2] = wq.x; w[k * 2 + 1] = wq.y;
            }
            unsigned long long hv2[2];
            #pragma unroll
            for (int mi = 0; mi < 2; mi++) {
                float hv = hs[(m0 + mi) * HS_STRIDE + d];
                PACK_DUP(hv2[mi], hv);
            }
            #pragma unroll
            for (int mi = 0; mi < 2; mi++)
                #pragma unroll
                for (int p = 0; p < 8; p++)
                    FMA2(acc[mi][p], hv2[mi], w[p]);
        }

        #pragma unroll
        for (int mi = 0; mi < 2; mi++) {
            #pragma unroll
            for (int p = 0; p < 8; p++) {
                float lo, hi;
                UNPACK2(lo, hi, acc[mi][p]);
                int j = j0 + (p >> 1) * 4 + (p & 1) * 2;
                float2 zv = make_float2(fmaxf(lo, 0.f), fmaxf(hi, 0.f));
                *(float2*)(zs + (m0 + mi) * H_DIM + j) = zv;
            }
        }
        __syncthreads();

        // ---- phase 2: logits = z@W2 + b2 ----
        unsigned long long a2[2][3];
        #pragma unroll
        for (int mi = 0; mi < 2; mi++)
            #pragma unroll
            for (int ci = 0; ci < 3; ci++) a2[mi][ci] = 0ull;

        #pragma unroll 4
        for (int j2 = 0; j2 < H_DIM / 2; j2++) {
            unsigned long long zz[2], ww[3];
            #pragma unroll
            for (int mi = 0; mi < 2; mi++)
                zz[mi] = *(const unsigned long long*)(zs + (mm0 + mi) * H_DIM + j2 * 2);
            #pragma unroll
            for (int ci = 0; ci < 3; ci++)
                ww[ci] = *(const unsigned long long*)(W2t + (c0 + ci) * W2T_STRIDE + j2 * 2);
            #pragma unroll
            for (int mi = 0; mi < 2; mi++)
                #pragma unroll
                for (int ci = 0; ci < 3; ci++)
                    FMA2(a2[mi][ci], zz[mi], ww[ci]);
        }

        #pragma unroll
        for (int mi = 0; mi < 2; mi++) {
            int node = node0 + mm0 + mi;
            #pragma unroll
            for (int ci = 0; ci < 3; ci++) {
                int c = c0 + ci;
                if (c < N_CLS) {
                    float lo, hi;
                    UNPACK2(lo, hi, a2[mi][ci]);
                    out[(size_t)node * N_CLS + c] = lo + hi + b2s[c];
                }
            }
        }
        __syncthreads();
    }
}

// ---------------- launch ----------------
extern "C" void kernel_launch(void* const* d_in, const int* in_sizes, int n_in,
                              void* d_out, int out_size) {
    const float* x   = (const float*)d_in[0];
    const int*   src = (const int*)d_in[1];
    const int*   dst = (const int*)d_in[2];
    const float* W1  = (const float*)d_in[3];
    const float* b1  = (const float*)d_in[4];
    const float* W2  = (const float*)d_in[5];
    const float* b2  = (const float*)d_in[6];
    float* out = (float*)d_out;

    cudaFuncSetAttribute(mlp_kernel, cudaFuncAttributeMaxDynamicSharedMemorySize,
                         MLP_SMEM_FLOATS * 4);

    __half* p0 = nullptr;
    __half* p1 = nullptr;
    cudaGetSymbolAddress((void**)&p0, g_h0);
    cudaGetSymbolAddress((void**)&p1, g_h1);

    int nb_nodes = (N_NODES + 255) / 256;
    int nb_edges = (N_EDGES + 255) / 256;

    zero_cnt_kernel<<<nb_nodes, 256>>>();
    count_kernel<<<nb_edges, 256>>>(dst);
    scan_kernel<<<1, SCAN_T>>>();
    norm_kernel<<<nb_nodes, 256>>>();
    fill_kernel<<<nb_edges, 256>>>(src, dst);

    int nb_init = (N_NODES * D_VEC + 255) / 256;
    init_g_kernel<<<nb_init, 256>>>((const float4*)x);

    int nb_prop = (N_NODES * 32 + 255) / 256;   // one warp per node
    for (int t = 0; t < K_STEPS; t++) {
        const __half* gin = (t & 1) ? p1 : p0;
        __half* gout      = (t & 1) ? p0 : p1;
        prop_kernel<<<nb_prop, 256>>>((const uint2*)gin, (uint2*)gout,
                                      (const float4*)x, (t == K_STEPS - 1) ? 1 : 0);
    }
    // after an even number of steps the result (h, fp16) lives in g_h0
    mlp_kernel<<<148, MLP_THREADS, MLP_SMEM_FLOATS * 4>>>(p0, W1, b1, W2, b2, out);
}

// round 4
// speedup vs baseline: 1.3886x; 1.3886x over previous
#include <cuda_runtime.h>
#include <cuda_bf16.h>
#include <math.h>

#define N_NODES 100000
#define N_EDGES 800000
#define D_DATA  100
#define H_DIM   256
#define N_CLS   47
#define K_STEPS 10
#define D_VEC   25          // D_DATA / 4 float4s per row

// ---------------- static device scratch ----------------
__device__ float g_buf0[(size_t)N_NODES * D_DATA];   // 40 MB
__device__ float g_buf1[(size_t)N_NODES * D_DATA];   // 40 MB
__device__ int   d_cnt[N_NODES];
__device__ int   d_ptr[N_NODES + 1];
__device__ int   d_cursor[N_NODES];
__device__ float d_norm[N_NODES];
__device__ float d_n2[N_NODES];
__device__ int   d_csr[N_EDGES];

// ---------------- f32x2 packed helpers ----------------
#define FMA2(acc, a, b) \
    asm("fma.rn.f32x2 %0, %1, %2, %0;" : "+l"(acc) : "l"(a), "l"(b))
#define PACK_DUP(dst, v) \
    asm("mov.b64 %0, {%1, %1};" : "=l"(dst) : "r"(__float_as_uint(v)))
#define UNPACK2(lo, hi, v) \
    asm("mov.b64 {%0, %1}, %2;" : "=f"(lo), "=f"(hi) : "l"(v))

// ---------------- CSR build ----------------
__global__ void zero_cnt_kernel() {
    int i = blockIdx.x * blockDim.x + threadIdx.x;
    if (i < N_NODES) d_cnt[i] = 0;
}

__global__ void count_kernel(const int* __restrict__ dst) {
    int e = blockIdx.x * blockDim.x + threadIdx.x;
    if (e < N_EDGES) atomicAdd(&d_cnt[dst[e]], 1);
}

#define SCAN_T 1024
#define SCAN_CH 98   // ceil(100000/1024)
__global__ void scan_kernel() {
    __shared__ int part[SCAN_T];
    int t = threadIdx.x;
    int beg = t * SCAN_CH;
    int end = beg + SCAN_CH; if (end > N_NODES) end = N_NODES;
    if (beg > N_NODES) beg = N_NODES;
    int s = 0;
    for (int i = beg; i < end; i++) s += d_cnt[i];
    part[t] = s;
    __syncthreads();
    for (int off = 1; off < SCAN_T; off <<= 1) {
        int v = (t >= off) ? part[t - off] : 0;
        __syncthreads();
        part[t] += v;
        __syncthreads();
    }
    int run = part[t] - s;
    for (int i = beg; i < end; i++) {
        d_ptr[i] = run;
        d_cursor[i] = run;
        run += d_cnt[i];
    }
    if (t == SCAN_T - 1) d_ptr[N_NODES] = part[SCAN_T - 1];
}

__global__ void norm_kernel() {
    int i = blockIdx.x * blockDim.x + threadIdx.x;
    if (i < N_NODES) {
        float dg = (float)d_cnt[i];
        float nm = rsqrtf(fmaxf(dg, 1.0f));
        d_norm[i] = nm;
        d_n2[i] = nm * nm;
    }
}

__global__ void fill_kernel(const int* __restrict__ src, const int* __restrict__ dst) {
    int e = blockIdx.x * blockDim.x + threadIdx.x;
    if (e < N_EDGES) {
        int d = dst[e];
        int p = atomicAdd(&d_cursor[d], 1);
        d_csr[p] = src[e];
    }
}

// ---------------- propagation ----------------
// g0 = x * norm  (x streamed, evict-first)
__global__ void init_g_kernel(const float4* __restrict__ x) {
    int idx = blockIdx.x * blockDim.x + threadIdx.x;
    if (idx < N_NODES * D_VEC) {
        int node = idx / D_VEC;
        float nm = d_norm[node];
        float4 v = __ldcs(&x[idx]);
        v.x *= nm; v.y *= nm; v.z *= nm; v.w *= nm;
        ((float4*)g_buf0)[idx] = v;
    }
}

// Warp per node. Warp-cooperative index load + 1 LDG.128 per edge (25 lanes).
// x read with __ldcs (streaming; keep L2 for the gather-hot g buffers).
// gout = s1 * sum_e gin[src] + s2 * x
__global__ void prop_kernel(const float4* __restrict__ gin,
                            float4* __restrict__ gout,
                            const float4* __restrict__ x,
                            int last) {
    int warp = (blockIdx.x * blockDim.x + threadIdx.x) >> 5;
    int lane = threadIdx.x & 31;
    if (warp >= N_NODES) return;
    int beg = d_ptr[warp];
    int end = d_ptr[warp + 1];

    float a0 = 0.f, a1 = 0.f, a2 = 0.f, a3 = 0.f;
    bool act = lane < D_VEC;

    for (int base = beg; base < end; base += 32) {
        int n = end - base; if (n > 32) n = 32;
        int idx = (lane < n) ? d_csr[base + lane] : 0;
        #pragma unroll 4
        for (int e = 0; e < n; e++) {
            int s = __shfl_sync(0xffffffffu, idx, e);
            if (act) {
                float4 v = gin[s * D_VEC + lane];
                a0 += v.x; a1 += v.y; a2 += v.z; a3 += v.w;
            }
        }
    }

    float ni = d_norm[warp];
    float s1, s2;
    if (last) { s1 = 0.9f * ni;         s2 = 0.1f; }
    else      { s1 = 0.9f * d_n2[warp]; s2 = 0.1f * ni; }

    if (act) {
        float4 xv = __ldcs(&x[warp * D_VEC + lane]);
        float4 o;
        o.x = s1 * a0 + s2 * xv.x;
        o.y = s1 * a1 + s2 * xv.y;
        o.z = s1 * a2 + s2 * xv.z;
        o.w = s1 * a3 + s2 * xv.w;
        if (last) __stcs(&gout[warp * D_VEC + lane], o);   // h consumed once
        else      gout[warp * D_VEC + lane] = o;
    }
}

// ---------------- fused MLP: logits = relu(h@W1+b1)@W2+b2 ----------------
// FFMA2 (fma.rn.f32x2) everywhere; conflict-free permuted W1 + transposed W2.
#define TM 32
#define HS_STRIDE 104
#define W2T_STRIDE 258
#define MLP_THREADS 256

#define SM_W1P  (D_DATA * H_DIM)            // 25600
#define SM_W2T  (48 * W2T_STRIDE)           // 12384
#define SM_B1   (H_DIM)
#define SM_B2   (48)
#define SM_HS   (TM * HS_STRIDE)            // 3328
#define SM_ZS   (TM * H_DIM)                // 8192
#define MLP_SMEM_FLOATS (SM_W1P + SM_W2T + SM_B1 + SM_B2 + SM_HS + SM_ZS)

__global__ void __launch_bounds__(MLP_THREADS, 1)
mlp_kernel(const float* __restrict__ h,
           const float* __restrict__ W1, const float* __restrict__ b1,
           const float* __restrict__ W2, const float* __restrict__ b2,
           float* __restrict__ out) {
    extern __shared__ float sm[];
    float* W1p = sm;                        // permuted, 16B-unit layout
    float* W2t = W1p + SM_W1P;              // [c][j], stride 258
    float* b1s = W2t + SM_W2T;
    float* b2s = b1s + SM_B1;
    float* hs  = b2s + SM_B2;               // [m][104]
    float* zs  = hs + SM_HS;                // [m][256]

    int tid = threadIdx.x;

    {
        const float4* W1v = (const float4*)W1;
        float4* W1pv = (float4*)W1p;
        for (int i = tid; i < D_DATA * 64; i += MLP_THREADS) {
            int d = i >> 6, u = i & 63;
            int k = u & 3, jg = u >> 2;
            W1pv[(d * 4 + k) * 16 + jg] = W1v[i];
        }
    }
    for (int i = tid; i < 48 * H_DIM; i += MLP_THREADS) {
        int c = i >> 8, j = i & 255;
        W2t[c * W2T_STRIDE + j] = (c < N_CLS) ? W2[j * N_CLS + c] : 0.f;
    }
    for (int i = tid; i < H_DIM; i += MLP_THREADS) b1s[i] = b1[i];
    if (tid < 48) b2s[tid] = (tid < N_CLS) ? b2[tid] : 0.f;
    __syncthreads();

    int jg = tid & 15, mg = tid >> 4;
    int j0 = jg * 16, m0 = mg * 2;
    int cg = tid & 15, mg2 = tid >> 4;
    int c0 = cg * 3, mm0 = mg2 * 2;

    const ulonglong2* W1q = (const ulonglong2*)W1p;

    int n_tiles = N_NODES / TM;   // 3125 exact
    for (int tile = blockIdx.x; tile < n_tiles; tile += gridDim.x) {
        int node0 = tile * TM;

        // stream h tile (read exactly once)
        {
            const float4* hrow = (const float4*)(h + (size_t)node0 * D_DATA);
            for (int i = tid; i < TM * D_VEC; i += MLP_THREADS) {
                int m = i / D_VEC, d4 = i - m * D_VEC;
                float4 v = __ldcs(&hrow[m * D_VEC + d4]);
                *(float4*)(hs + m * HS_STRIDE + d4 * 4) = v;
            }
        }
        __syncthreads();

        // ---- phase 1: z = relu(h@W1 + b1) ----
        unsigned long long acc[2][8];
        #pragma unroll
        for (int k = 0; k < 4; k++) {
            unsigned long long blo = *(const unsigned long long*)(b1s + j0 + k * 4);
            unsigned long long bhi = *(const unsigned long long*)(b1s + j0 + k * 4 + 2);
            acc[0][k * 2]     = blo; acc[0][k * 2 + 1] = bhi;
            acc[1][k * 2]     = blo; acc[1][k * 2 + 1] = bhi;
        }

        #pragma unroll 2
        for (int d = 0; d < D_DATA; d++) {
            unsigned long long w[8];
            #pragma unroll
            for (int k = 0; k < 4; k++) {
                ulonglong2 wq = W1q[(d * 4 + k) * 16 + jg];
                w[k * 2] = wq.x; w[k * 2 + 1] = wq.y;
            }
            unsigned long long hv2[2];
            #pragma unroll
            for (int mi = 0; mi < 2; mi++) {
                float hv = hs[(m0 + mi) * HS_STRIDE + d];
                PACK_DUP(hv2[mi], hv);
            }
            #pragma unroll
            for (int mi = 0; mi < 2; mi++)
                #pragma unroll
                for (int p = 0; p < 8; p++)
                    FMA2(acc[mi][p], hv2[mi], w[p]);
        }

        #pragma unroll
        for (int mi = 0; mi < 2; mi++) {
            #pragma unroll
            for (int p = 0; p < 8; p++) {
                float lo, hi;
                UNPACK2(lo, hi, acc[mi][p]);
                int j = j0 + (p >> 1) * 4 + (p & 1) * 2;
                float2 zv = make_float2(fmaxf(lo, 0.f), fmaxf(hi, 0.f));
                *(float2*)(zs + (m0 + mi) * H_DIM + j) = zv;
            }
        }
        __syncthreads();

        // ---- phase 2: logits = z@W2 + b2 ----
        unsigned long long a2[2][3];
        #pragma unroll
        for (int mi = 0; mi < 2; mi++)
            #pragma unroll
            for (int ci = 0; ci < 3; ci++) a2[mi][ci] = 0ull;

        #pragma unroll 4
        for (int j2 = 0; j2 < H_DIM / 2; j2++) {
            unsigned long long zz[2], ww[3];
            #pragma unroll
            for (int mi = 0; mi < 2; mi++)
                zz[mi] = *(const unsigned long long*)(zs + (mm0 + mi) * H_DIM + j2 * 2);
            #pragma unroll
            for (int ci = 0; ci < 3; ci++)
                ww[ci] = *(const unsigned long long*)(W2t + (c0 + ci) * W2T_STRIDE + j2 * 2);
            #pragma unroll
            for (int mi = 0; mi < 2; mi++)
                #pragma unroll
                for (int ci = 0; ci < 3; ci++)
                    FMA2(a2[mi][ci], zz[mi], ww[ci]);
        }

        #pragma unroll
        for (int mi = 0; mi < 2; mi++) {
            int node = node0 + mm0 + mi;
            #pragma unroll
            for (int ci = 0; ci < 3; ci++) {
                int c = c0 + ci;
                if (c < N_CLS) {
                    float lo, hi;
                    UNPACK2(lo, hi, a2[mi][ci]);
                    out[(size_t)node * N_CLS + c] = lo + hi + b2s[c];
                }
            }
        }
        __syncthreads();
    }
}

// ---------------- launch ----------------
extern "C" void kernel_launch(void* const* d_in, const int* in_sizes, int n_in,
                              void* d_out, int out_size) {
    const float* x   = (const float*)d_in[0];
    const int*   src = (const int*)d_in[1];
    const int*   dst = (const int*)d_in[2];
    const float* W1  = (const float*)d_in[3];
    const float* b1  = (const float*)d_in[4];
    const float* W2  = (const float*)d_in[5];
    const float* b2  = (const float*)d_in[6];
    float* out = (float*)d_out;

    cudaFuncSetAttribute(mlp_kernel, cudaFuncAttributeMaxDynamicSharedMemorySize,
                         MLP_SMEM_FLOATS * 4);

    float* p0 = nullptr;
    float* p1 = nullptr;
    cudaGetSymbolAddress((void**)&p0, g_buf0);
    cudaGetSymbolAddress((void**)&p1, g_buf1);

    int nb_nodes = (N_NODES + 255) / 256;
    int nb_edges = (N_EDGES + 255) / 256;

    zero_cnt_kernel<<<nb_nodes, 256>>>();
    count_kernel<<<nb_edges, 256>>>(dst);
    scan_kernel<<<1, SCAN_T>>>();
    norm_kernel<<<nb_nodes, 256>>>();
    fill_kernel<<<nb_edges, 256>>>(src, dst);

    int nb_init = (N_NODES * D_VEC + 255) / 256;
    init_g_kernel<<<nb_init, 256>>>((const float4*)x);

    int nb_prop = (N_NODES * 32 + 255) / 256;   // one warp per node
    for (int t = 0; t < K_STEPS; t++) {
        const float* gin = (t & 1) ? p1 : p0;
        float* gout      = (t & 1) ? p0 : p1;
        prop_kernel<<<nb_prop, 256>>>((const float4*)gin, (float4*)gout,
                                      (const float4*)x, (t == K_STEPS - 1) ? 1 : 0);
    }
    // after an even number of steps the result lives in g_buf0
    mlp_kernel<<<148, MLP_THREADS, MLP_SMEM_FLOATS * 4>>>(p0, W1, b1, W2, b2, out);
}